// round 7
// baseline (speedup 1.0000x reference)
#include <cuda_runtime.h>
#include <cuda_bf16.h>

#define TT 1024
#define BB 4096
#define TOTAL4 (BB * TT / 4)        // 1048576 float4-groups
#define NBLK 296                    // 512-thread blocks; 296 = 8*37
#define RBLKS 120                   // 96 S-blocks + 24 count-blocks
#define NEGBIG (-1.0e30f)

typedef unsigned long long u64;

// ---- device scratch (static; counter self-resets each launch) ----
__device__ __align__(16) float        g_S[NBLK * 3072];   // [blk][p=3t+c]
__device__ __align__(16) unsigned int g_C[NBLK * 768];    // [blk][3*(t>>2)+c], byte=t&3
__device__ __align__(16) float        g_pS[3072];
__device__ __align__(16) int          g_pN[3072];
__device__ unsigned int g_rcnt;

// ======================= packed f32x2 helpers =======================
__device__ __forceinline__ u64 pk2(float lo, float hi) {
    u64 r; asm("mov.b64 %0,{%1,%2};" : "=l"(r) : "f"(lo), "f"(hi)); return r;
}
__device__ __forceinline__ void upk2(u64 v, float& lo, float& hi) {
    asm("mov.b64 {%0,%1},%2;" : "=f"(lo), "=f"(hi) : "l"(v));
}
__device__ __forceinline__ u64 f2add(u64 a, u64 b) {
    u64 d; asm("add.rn.f32x2 %0,%1,%2;" : "=l"(d) : "l"(a), "l"(b)); return d;
}
__device__ __forceinline__ u64 f2mul(u64 a, u64 b) {
    u64 d; asm("mul.rn.f32x2 %0,%1,%2;" : "=l"(d) : "l"(a), "l"(b)); return d;
}
__device__ __forceinline__ u64 f2fma(u64 a, u64 b, u64 c) {
    u64 d; asm("fma.rn.f32x2 %0,%1,%2,%3;" : "=l"(d) : "l"(a), "l"(b), "l"(c)); return d;
}
__device__ __forceinline__ u64 bc2(float x) {
    u64 r; asm("mov.b64 %0,{%1,%1};" : "=l"(r) : "f"(x)); return r;
}

// ======================= packed Stirling (y >= 5 both lanes) =======================
// r computed via merged reciprocal: rcp(yx*yy) * y_other (used only in small corrections).
template<bool PS>
__device__ __forceinline__ void stirl2(u64 y2, u64& lg2, u64& ps2) {
    float yx, yy; upk2(y2, yx, yy);
    float im = __fdividef(1.0f, yx * yy);
    u64 r2 = pk2(im * yy, im * yx);
    u64 L2 = pk2(__logf(yx), __logf(yy));
    u64 rsq   = f2mul(r2, r2);
    u64 inner = f2fma(rsq, bc2(-2.7777778e-3f), bc2(8.3333333e-2f));
    u64 tail  = f2fma(r2, inner, f2fma(y2, bc2(-1.0f), bc2(0.91893853f)));
    lg2 = f2fma(f2add(y2, bc2(-0.5f)), L2, tail);
    if (PS) {
        u64 t = f2fma(rsq, bc2(8.3333333e-3f), bc2(-8.3333333e-2f)); // rsq/120 - 1/12
        ps2 = f2fma(rsq, t, f2fma(r2, bc2(-0.5f), L2));              // L - r/2 + rsq*t
    }
}

// ======================= packed pairwise KL =======================
__device__ __forceinline__ void kl_pair(
    float l00, float l01, float tw0, float tc0,
    float l10, float l11, float tw1, float tc1,
    float& kl0, float& kl1)
{
    // sigmoids: scalar MUFU exp + one merged rcp per element
    float e00 = __expf(-l00), e01 = __expf(-l01);
    float e10 = __expf(-l10), e11 = __expf(-l11);
    float d00 = 1.0f + e00, d01 = 1.0f + e01;
    float d10 = 1.0f + e10, d11 = 1.0f + e11;
    float i0 = __fdividef(1.0f, d00 * d01);
    float i1 = __fdividef(1.0f, d10 * d11);
    u64 pw2  = pk2(i0 * d01, i1 * d11);    // 1/d00, 1/d10
    u64 pcs2 = pk2(i0 * d00, i1 * d10);    // 1/d01, 1/d11

    const u64 cm1 = bc2(-1.0f), c1 = bc2(1.0f);
    const u64 c2v = bc2(2.0f),  c3 = bc2(3.0f), c4 = bc2(4.0f);

    u64 tw2 = pk2(tw0, tw1), tc2 = pk2(tc0, tc1);
    u64 pc2 = f2fma(pcs2, bc2(1023.0f), bc2(5.0f));
    u64 sp2 = f2add(tc2, c2v);
    u64 sq2 = f2add(pc2, c2v);
    u64 ta2 = f2fma(tc2, tw2, c1);
    u64 tb2 = f2fma(ta2, cm1, sp2);
    u64 pa2 = f2fma(pc2, pw2, c1);
    u64 pb2 = f2fma(pa2, cm1, sq2);

    u64 uta2 = f2mul(ta2, f2add(ta2, c3)), Pta2 = f2mul(uta2, f2add(uta2, c2v));
    u64 utb2 = f2mul(tb2, f2add(tb2, c3)), Ptb2 = f2mul(utb2, f2add(utb2, c2v));
    u64 upa2 = f2mul(pa2, f2add(pa2, c3)), Ppa2 = f2mul(upa2, f2add(upa2, c2v));
    u64 upb2 = f2mul(pb2, f2add(pb2, c3)), Ppb2 = f2mul(upb2, f2add(upb2, c2v));

    u64 lgta2, psta2; stirl2<true >(f2add(ta2, c4), lgta2, psta2);
    u64 lgtb2, pstb2; stirl2<true >(f2add(tb2, c4), lgtb2, pstb2);
    u64 lgsp2, pssp2; stirl2<true >(sp2,            lgsp2, pssp2);
    u64 lgpa2, du0;   stirl2<false>(f2add(pa2, c4), lgpa2, du0);
    u64 lgpb2, du1;   stirl2<false>(f2add(pb2, c4), lgpb2, du1);
    u64 lgsq2, du2;   stirl2<false>(sq2,            lgsq2, du2);

    u64 da2 = f2fma(pa2, cm1, ta2);
    u64 db2 = f2fma(pb2, cm1, tb2);
    u64 Aa2 = f2mul(f2fma(uta2, c2v, c2v), f2fma(ta2, c2v, c3));
    u64 Ab2 = f2mul(f2fma(utb2, c2v, c2v), f2fma(tb2, c2v, c3));
    u64 Ptt2 = f2mul(Pta2, Ptb2);
    u64 num2 = f2fma(f2mul(da2, Aa2), Ptb2, f2mul(f2mul(db2, Ab2), Pta2));
    float nx, ny, px, py; upk2(num2, nx, ny); upk2(Ptt2, px, py);
    u64 corr2 = pk2(__fdividef(nx, px), __fdividef(ny, py));

    u64 PQ2 = f2mul(Ppa2, Ppb2);
    float qx, qy; upk2(PQ2, qx, qy);
    u64 ld2 = pk2(__logf(px) - __logf(qx), __logf(py) - __logf(qy));

    u64 acc = f2add(f2add(lgpa2, lgpb2), lgsp2);
    acc = f2fma(lgta2, cm1, acc);
    acc = f2fma(lgtb2, cm1, acc);
    acc = f2fma(lgsq2, cm1, acc);
    acc = f2add(acc, ld2);
    acc = f2fma(da2, psta2, acc);
    acc = f2fma(db2, pstb2, acc);
    u64 spq2 = f2fma(sp2, cm1, sq2);
    acc = f2fma(spq2, pssp2, acc);
    acc = f2fma(corr2, cm1, acc);
    upk2(acc, kl0, kl1);
}

// ======================= kernel 1: main KL pass =======================
// 296 blocks x 512 threads. Thread owns t = 4*(tid&255)+j; the two thread-halves
// share t-sets and fold in smem before one small coalesced slab write.
__global__ void __launch_bounds__(512)
main_kernel(const float* __restrict__ logits, const float* __restrict__ tgt) {
    const int tid = threadIdx.x;
    const int q = tid >> 8, r = tid & 255;
    const float4* tg4 = reinterpret_cast<const float4*>(tgt);
    const float4* lg4 = reinterpret_cast<const float4*>(logits);

    float s[4][3];
#pragma unroll
    for (int j = 0; j < 4; j++) { s[j][0] = 0.0f; s[j][1] = 0.0f; s[j][2] = 0.0f; }
    unsigned int cn[3] = {0u, 0u, 0u};

#pragma unroll 1
    for (int g = blockIdx.x * 512 + tid; g < TOTAL4; g += NBLK * 512) {
        float4 a = tg4[g * 3 + 0];
        float4 b = tg4[g * 3 + 1];
        float4 c = tg4[g * 3 + 2];
        float4 d = lg4[g * 2 + 0];
        float4 e = lg4[g * 2 + 1];
        float tv[12] = {a.x, a.y, a.z, a.w, b.x, b.y, b.z, b.w, c.x, c.y, c.z, c.w};
        float lv[8]  = {d.x, d.y, d.z, d.w, e.x, e.y, e.z, e.w};

        float tw[4], tc[4], kl[4];
        int dx[4];
#pragma unroll
        for (int j = 0; j < 4; j++) {
            float x2 = tv[3 * j + 2];
            bool m = (x2 > NEGBIG);
            tw[j] = m ? tv[3 * j]     : 0.5f;
            tc[j] = m ? tv[3 * j + 1] : 5.0f;
            dx[j] = m ? (int)x2 : -1;
        }
        kl_pair(lv[0], lv[1], tw[0], tc[0], lv[2], lv[3], tw[1], tc[1], kl[0], kl[1]);
        kl_pair(lv[4], lv[5], tw[2], tc[2], lv[6], lv[7], tw[3], tc[3], kl[2], kl[3]);
#pragma unroll
        for (int j = 0; j < 4; j++) {
            s[j][0] += (dx[j] == 0) ? kl[j] : 0.0f;
            s[j][1] += (dx[j] == 1) ? kl[j] : 0.0f;
            s[j][2] += (dx[j] == 2) ? kl[j] : 0.0f;
            cn[0] += (dx[j] == 0) ? (1u << (8 * j)) : 0u;
            cn[1] += (dx[j] == 1) ? (1u << (8 * j)) : 0u;
            cn[2] += (dx[j] == 2) ? (1u << (8 * j)) : 0u;
        }
    }

    // 2-phase fixed-order half fold in smem
    __shared__ float        sh[3072];
    __shared__ unsigned int shc[768];
    if (q == 0) {
#pragma unroll
        for (int j = 0; j < 4; j++)
#pragma unroll
            for (int c = 0; c < 3; c++) sh[12 * r + 3 * j + c] = s[j][c];
#pragma unroll
        for (int c = 0; c < 3; c++) shc[3 * r + c] = cn[c];
    }
    __syncthreads();
    if (q == 1) {
#pragma unroll
        for (int j = 0; j < 4; j++)
#pragma unroll
            for (int c = 0; c < 3; c++) sh[12 * r + 3 * j + c] += s[j][c];
#pragma unroll
        for (int c = 0; c < 3; c++) shc[3 * r + c] += cn[c];
    }
    __syncthreads();

    if (q == 0) {
        const float4* shv = reinterpret_cast<const float4*>(&sh[12 * r]);
        float4* so = reinterpret_cast<float4*>(&g_S[blockIdx.x * 3072 + 12 * r]);
        so[0] = shv[0]; so[1] = shv[1]; so[2] = shv[2];
        unsigned int* co = &g_C[blockIdx.x * 768 + 3 * r];
        co[0] = shc[3 * r]; co[1] = shc[3 * r + 1]; co[2] = shc[3 * r + 2];
    }
}

// ======================= kernel 2: reduce + finalize =======================
// Blocks 0..95: S (p = blk*32+lane; warp w sums b = w, w+8, ..., 37 iters).
// Blocks 96..119: packed counts (chunks of 18: 18*14=252 <= 255, no carry).
__global__ void __launch_bounds__(256)
reduce_kernel(float* __restrict__ out) {
    const int tid = threadIdx.x;
    const int w = tid >> 5, l = tid & 31;
    __shared__ float sS[8][32];
    __shared__ int   sN[8][32][4];

    if (blockIdx.x < 96) {
        const int p = blockIdx.x * 32 + l;
        float acc = 0.0f;
#pragma unroll
        for (int i = 0; i < 37; i++)
            acc += g_S[(w + 8 * i) * 3072 + p];          // coalesced per warp
        sS[w][l] = acc;
        __syncthreads();
        if (w == 0) {
            float ssum = 0.0f;
#pragma unroll
            for (int i = 0; i < 8; i++) ssum += sS[i][l];
            g_pS[p] = ssum;
        }
    } else {
        const int wi = (blockIdx.x - 96) * 32 + l;       // count word 0..767
        int n[4] = {0, 0, 0, 0};
        int b = w;
#pragma unroll
        for (int chunk = 0; chunk < 3; chunk++) {
            unsigned int acc = 0;
            int cnt = (chunk < 2) ? 18 : 1;
#pragma unroll
            for (int i = 0; i < 18; i++) {
                if (i < cnt) { acc += g_C[b * 768 + wi]; b += 8; }
            }
            n[0] += (int)(acc & 0xFFu);
            n[1] += (int)((acc >> 8) & 0xFFu);
            n[2] += (int)((acc >> 16) & 0xFFu);
            n[3] += (int)(acc >> 24);
        }
#pragma unroll
        for (int j = 0; j < 4; j++) sN[w][l][j] = n[j];
        __syncthreads();
        if (w == 0) {
            int t4 = wi / 3, c = wi - 3 * t4;            // byte j -> t = 4*t4+j
#pragma unroll
            for (int j = 0; j < 4; j++) {
                int nsum = 0;
#pragma unroll
                for (int i = 0; i < 8; i++) nsum += sN[i][l][j];
                g_pN[12 * t4 + 3 * j + c] = nsum;
            }
        }
    }

    __threadfence();
    __syncthreads();
    __shared__ bool amLast;
    if (tid == 0)
        amLast = (atomicAdd(&g_rcnt, 1u) == (unsigned)(RBLKS - 1));
    __syncthreads();
    if (!amLast) return;
    __threadfence();

    // fold: thread owns t = 4*tid+j; 12 S + 12 N contiguous reads
    const float4* ps4 = reinterpret_cast<const float4*>(&g_pS[12 * tid]);
    const int4*   pn4 = reinterpret_cast<const int4*>(&g_pN[12 * tid]);
    float acc = 0.0f;
#pragma unroll
    for (int k = 0; k < 3; k++) {
        float4 S = ps4[k];
        int4   N = pn4[k];
        acc += (N.x > 0) ? __fdividef(S.x, 3.0f * (float)N.x) : 0.0f;
        acc += (N.y > 0) ? __fdividef(S.y, 3.0f * (float)N.y) : 0.0f;
        acc += (N.z > 0) ? __fdividef(S.z, 3.0f * (float)N.z) : 0.0f;
        acc += (N.w > 0) ? __fdividef(S.w, 3.0f * (float)N.w) : 0.0f;
    }

#pragma unroll
    for (int off = 16; off > 0; off >>= 1)
        acc += __shfl_xor_sync(0xffffffffu, acc, off);
    __shared__ float ws[8];
    if ((tid & 31) == 0) ws[tid >> 5] = acc;
    __syncthreads();
    if (tid == 0) {
        float tot = 0.0f;
#pragma unroll
        for (int i = 0; i < 8; i++) tot += ws[i];
        out[0] = tot * (1.0f / (float)TT);
        g_rcnt = 0;                                      // reset for next replay
    }
}

// ======================= launch =======================
extern "C" void kernel_launch(void* const* d_in, const int* in_sizes, int n_in,
                              void* d_out, int out_size) {
    const float* logits;
    const float* targets;
    if (in_sizes[0] == BB * TT * 2) {
        logits  = (const float*)d_in[0];
        targets = (const float*)d_in[1];
    } else {
        logits  = (const float*)d_in[1];
        targets = (const float*)d_in[0];
    }
    float* out = (float*)d_out;

    main_kernel<<<NBLK, 512>>>(logits, targets);
    reduce_kernel<<<RBLKS, 256>>>(out);
}